// round 2
// baseline (speedup 1.0000x reference)
#include <cuda_runtime.h>
#include <math.h>

#define BB 4
#define DD 64
#define NV (DD*DD*DD)        // 262144 voxels per batch (2^18)
#define TOT (BB*NV)          // 1048576
#define NP 512               // points per batch

// tile: 8(x) x 8(y) x 64(z, contiguous) = 4096 voxels
#define TILE_VOX 4096
#define TILES_PER_BATCH 64   // 8 x 8
#define NTILES (BB*TILES_PER_BATCH)

// boundary-merge work items: BB batches * 2 dirs * 7 planes * 64*64
#define NBW (BB*2*7*4096)

// -------- scratch (device globals: no allocations allowed) --------
__device__ double g_part[256];
__device__ float  g_mean;
__device__ int    g_parent[TOT];   // -1 = background, else union-find parent (global flat idx)
__device__ int    g_num[BB];       // component count per batch

// -------- 1) deterministic mean: two fixed-order tree reductions ----------
__global__ void k_reduce1(const float* __restrict__ x) {
    __shared__ double sh[256];
    const int t = threadIdx.x, bk = blockIdx.x;
    const int CH4 = (TOT / 256) / 4;       // 1024 float4 per block
    const float4* __restrict__ x4 = (const float4*)x + bk * CH4;
    double s = 0.0;
    for (int i = t; i < CH4; i += 256) {
        float4 v = x4[i];
        s += ((double)v.x + (double)v.y) + ((double)v.z + (double)v.w);
    }
    sh[t] = s; __syncthreads();
    for (int o = 128; o > 0; o >>= 1) { if (t < o) sh[t] += sh[t + o]; __syncthreads(); }
    if (t == 0) g_part[bk] = sh[0];
}

__global__ void k_reduce2() {
    __shared__ double sh[256];
    const int t = threadIdx.x;
    sh[t] = g_part[t]; __syncthreads();
    for (int o = 128; o > 0; o >>= 1) { if (t < o) sh[t] += sh[t + o]; __syncthreads(); }
    if (t == 0) g_mean = (float)(sh[0] / (double)TOT);
    if (t < BB) g_num[t] = 0;              // re-zero every replay
}

// -------- shared-memory union-find ----------
__device__ __forceinline__ int sfind(const int* sp, int i) {
    int p = sp[i];
    while (p != i) { i = p; p = sp[i]; }
    return i;
}

__device__ __forceinline__ void sunite(int* sp, int a, int b) {
    while (true) {
        a = sfind(sp, a);
        b = sfind(sp, b);
        if (a == b) return;
        if (a > b) { int t = a; a = b; b = t; }
        int old = atomicMin(&sp[b], a);
        if (old == b) return;
        b = old;
    }
}

// -------- 2) per-tile CCL in shared memory (fused mask), write global parents --
// local l = lx*512 + ly*64 + lz  (monotone wrt global flat index)
__global__ void k_local(const float* __restrict__ x) {
    __shared__ int sp[TILE_VOX];
    const int t = threadIdx.x;
    const int blk = blockIdx.x;                 // 0..255
    const int b  = blk >> 6;
    const int tx = (blk >> 3) & 7;              // tile x
    const int ty = blk & 7;                     // tile y
    const int base = (b << 18) + (tx << 15) + (ty << 9);  // (tx*8)<<12, (ty*8)<<6

    const float mean = g_mean;

    // init: mask from logits
    #pragma unroll
    for (int k = 0; k < 16; k++) {
        const int l = t + (k << 8);
        const int lz = l & 63, ly = (l >> 6) & 7, lx = l >> 9;
        const int g = base + (lx << 12) + (ly << 6) + lz;
        sp[l] = (x[g] > mean) ? l : -1;
    }
    __syncthreads();

    // merge local negative-direction edges
    #pragma unroll
    for (int k = 0; k < 16; k++) {
        const int l = t + (k << 8);
        if (sp[l] < 0) continue;
        const int lz = l & 63, ly = (l >> 6) & 7, lx = l >> 9;
        if (lz > 0 && sp[l - 1]   >= 0) sunite(sp, l, l - 1);
        if (ly > 0 && sp[l - 64]  >= 0) sunite(sp, l, l - 64);
        if (lx > 0 && sp[l - 512] >= 0) sunite(sp, l, l - 512);
    }
    __syncthreads();

    // flatten locally and write global parent (root -> its own global index)
    #pragma unroll
    for (int k = 0; k < 16; k++) {
        const int l = t + (k << 8);
        const int lz = l & 63, ly = (l >> 6) & 7, lx = l >> 9;
        const int g = base + (lx << 12) + (ly << 6) + lz;
        int v = sp[l];
        if (v < 0) { g_parent[g] = -1; continue; }
        const int r = sfind(sp, l);
        const int rg = base + ((r >> 9) << 12) + (((r >> 6) & 7) << 6) + (r & 63);
        g_parent[g] = rg;
    }
}

// -------- global union-find (lock-free atomicMin link-at-root) ----------
__device__ __forceinline__ int uf_find(int i) {
    int p = g_parent[i];
    while (p != i) { i = p; p = g_parent[i]; }
    return i;
}

__device__ __forceinline__ void uf_unite(int a, int b) {
    while (true) {
        a = uf_find(a);
        b = uf_find(b);
        if (a == b) return;
        if (a > b) { int t = a; a = b; b = t; }
        int old = atomicMin(&g_parent[b], a);
        if (old == b) return;
        b = old;
    }
}

// -------- 3) merge cross-tile boundary edges only ----------
// t decodes: z (6b) | row (6b) | plane p (%7) | dir (1b) | batch
__global__ void k_bmerge() {
    const int t = blockIdx.x * blockDim.x + threadIdx.x;
    if (t >= NBW) return;
    const int z   = t & 63;
    const int row = (t >> 6) & 63;
    int t3 = t >> 12;
    const int p   = t3 % 7;                 // plane 0..6 -> coord 8..56
    int t4 = t3 / 7;
    const int dir = t4 & 1;
    const int b   = t4 >> 1;
    const int coord = (p + 1) << 3;
    int xx, yy, nbr_off;
    if (dir == 0) { xx = coord; yy = row; nbr_off = -4096; }  // -x edge
    else          { yy = coord; xx = row; nbr_off = -64;   }  // -y edge
    const int i = (b << 18) + (xx << 12) + (yy << 6) + z;
    if (g_parent[i] < 0) return;
    if (g_parent[i + nbr_off] < 0) return;
    uf_unite(i, i + nbr_off);
}

// -------- 4) count component roots per batch (no flatten needed) ----------
__global__ void k_count() {
    const int i = blockIdx.x * blockDim.x + threadIdx.x;
    if (i >= TOT) return;
    if (g_parent[i] == i) atomicAdd(&g_num[i >> 18], 1);
}

// -------- 5) fused point lookup + per-batch RMS (O(P^2) in shared) --------
__global__ void k_rms(const float* __restrict__ pts, float* __restrict__ out) {
    __shared__ int sh[NP];
    __shared__ int s_h0, s_sq, s_nc;
    const int b = blockIdx.x, t = threadIdx.x;

    const float* p = pts + (b * NP + t) * 3;
    const int s0 = (int)p[0];              // pts in [0, 64-1e-3): trunc == floor
    const int s1 = (int)p[1];
    const int s2 = (int)p[2];
    const int flat = (b << 18) + (s0 << 12) + (s1 << 6) + s2;
    const int pr = g_parent[flat];
    const int h = (pr >= 0) ? (uf_find(flat) + 1) : 0;

    sh[t] = h;
    if (t == 0) { s_h0 = 0; s_sq = 0; s_nc = 0; }
    __syncthreads();

    int cnt = 0, first = -1;
    #pragma unroll 8
    for (int j = 0; j < NP; j++) {
        if (sh[j] == h) { if (cnt == 0) first = j; cnt++; }
    }
    if (h == 0) {
        atomicAdd(&s_h0, 1);
    } else if (first == t) {               // representative of a hit component
        const int d = cnt - 1;
        atomicAdd(&s_sq, d * d);           // (1-cnt)^2, exact in int
        atomicAdd(&s_nc, 1);
    }
    __syncthreads();
    if (t == 0) {
        const float num = (float)g_num[b];
        const float sq = (float)s_h0 * (float)s_h0
                       + (float)s_sq
                       + (num - (float)s_nc);   // unhit components
        out[b] = sqrtf(sq / (num + 1.0f));
    }
}

// -------- launcher ----------
extern "C" void kernel_launch(void* const* d_in, const int* in_sizes, int n_in,
                              void* d_out, int out_size) {
    const float* logits = (const float*)d_in[0];
    const float* pts    = (const float*)d_in[1];
    if (n_in >= 2 && in_sizes[0] != TOT * 1) {   // defensive input-order check
        logits = (const float*)d_in[1];
        pts    = (const float*)d_in[0];
    }
    k_reduce1<<<256, 256>>>(logits);
    k_reduce2<<<1, 256>>>();
    k_local<<<NTILES, 256>>>(logits);
    k_bmerge<<<(NBW + 255) / 256, 256>>>();
    k_count<<<TOT / 256, 256>>>();
    k_rms<<<BB, NP>>>(pts, (float*)d_out);
}